// round 16
// baseline (speedup 1.0000x reference)
#include <cuda_runtime.h>

#define B_  8
#define H_  8
#define QS_ 64
#define KS_ 512
#define A_  64
#define DH_ 64
#define KC_ 128
#define NC_ 4
#define QD_ 512
#define KD_ 512
#define NF_ 35   // a in [0,NF): FMA-pipe cubic-Newton path; a in [NF,64): MUFU tanh
#define NM_ (A_ - NF_)

typedef unsigned long long ull;

__device__ float g_pout[B_*H_*NC_*QS_*DH_];   // 4 MB
__device__ float g_Sx[B_*H_*NC_*QS_];
__device__ int   g_cnt[B_*H_];                // zero-init; self-resetting

__device__ __forceinline__ float fast_tanh(float v) {
    float y; asm("tanh.approx.f32 %0, %1;" : "=f"(y) : "f"(v)); return y;
}
__device__ __forceinline__ ull pk2(float x, float y) {
    ull r; asm("mov.b64 %0, {%1, %2};" : "=l"(r) : "f"(x), "f"(y)); return r;
}
__device__ __forceinline__ float2 upk2(ull v) {
    float2 r; asm("mov.b64 {%0, %1}, %2;" : "=f"(r.x), "=f"(r.y) : "l"(v)); return r;
}
__device__ __forceinline__ ull ffma2(ull a, ull b, ull c) {
    ull d; asm("fma.rn.f32x2 %0, %1, %2, %3;" : "=l"(d) : "l"(a), "l"(b), "l"(c)); return d;
}
__device__ __forceinline__ ull fadd2(ull a, ull b) {
    ull d; asm("add.rn.f32x2 %0, %1, %2;" : "=l"(d) : "l"(a), "l"(b)); return d;
}
__device__ __forceinline__ ull rcp_seed2(ull nv) {
    unsigned lo, hi;
    asm("mov.b64 {%0, %1}, %2;" : "=r"(lo), "=r"(hi) : "l"(nv));
    lo = 0xFEF311C3u - lo;
    hi = 0xFEF311C3u - hi;
    ull r; asm("mov.b64 %0, {%1, %2};" : "=l"(r) : "r"(lo), "r"(hi));
    return r;
}
__device__ __forceinline__ unsigned tf32c(float f) {
    unsigned r; asm("cvt.rna.tf32.f32 %0, %1;" : "=r"(r) : "f"(f)); return r;
}
__device__ __forceinline__ void mma_tf32(float* d, const unsigned* a, const unsigned* b) {
    asm volatile("mma.sync.aligned.m16n8k8.row.col.f32.tf32.tf32.f32 "
        "{%0,%1,%2,%3}, {%4,%5,%6,%7}, {%8,%9}, {%0,%1,%2,%3};"
        : "+f"(d[0]), "+f"(d[1]), "+f"(d[2]), "+f"(d[3])
        : "r"(a[0]), "r"(a[1]), "r"(a[2]), "r"(a[3]), "r"(b[0]), "r"(b[1]));
}

// ---------------- smem layout (bytes) ----------------
// s_xv @0 f32[128][68]; s_q @34816 f32[64][64] (stride 64, ends 51200);
// s_W1 @51200 f32[64][68]; s_kp @34816 (alias, f32[64][132]);
// s_Wk @68608; s_p @68608 (alias, f32[64][132]); s_qp @86016 f32[64][68];
// s_bias @103424; s_w2 @103680; s_last @103936
#define SMF_BYTES 104192

__global__ void __launch_bounds__(256, 2) fused_kernel(
    const float* __restrict__ x, const float* __restrict__ query,
    const float* __restrict__ W, const float* __restrict__ bias,
    const float* __restrict__ w2, const unsigned char* __restrict__ mask,
    float* __restrict__ out)
{
    extern __shared__ char sm[];
    float* s_xv  = (float*)(sm);
    float* s_q   = (float*)(sm + 34816);
    float* s_W1  = (float*)(sm + 51200);
    float* s_kp  = (float*)(sm + 34816);
    float* s_Wk  = (float*)(sm + 68608);
    float* s_p   = (float*)(sm + 68608);
    float* s_qp  = (float*)(sm + 86016);
    float* s_bias= (float*)(sm + 103424);
    float* s_w2  = (float*)(sm + 103680);
    int*   s_last= (int*)(sm + 103936);

    const int kc = blockIdx.x, h = blockIdx.y, b = blockIdx.z;
    const int tid = threadIdx.x;
    const int tx = tid & 15, ty = tid >> 4;
    const int warp = tid >> 5, lane = tid & 31;
    const int grp = lane >> 2, thr = lane & 3;
    const int bh = b * H_ + h;
    const float LOG2E2 = 2.885390082f;   // 2*log2(e)

    if (tid < 64) { s_bias[tid] = bias[tid]; s_w2[tid] = w2[tid]; }

    // ---- phase 1: stage query [64][64] (stride 64) + Wq ----
#pragma unroll
    for (int i = 0; i < 4; i++) {
        int idx = tid + 256 * i; int q = idx >> 4, d4 = idx & 15;
        *(float4*)&s_q[q * 64 + d4 * 4] =
            *(const float4*)&query[(size_t)(b * QS_ + q) * QD_ + h * DH_ + d4 * 4];
    }
#pragma unroll
    for (int i = 0; i < 4; i++) {
        int idx = tid + 256 * i; int a = idx >> 4, d4 = idx & 15;
        *(float4*)&s_W1[a * 68 + d4 * 4] = *(const float4*)&W[a * 128 + 64 + d4 * 4];
    }
    __syncthreads();

    // ---- qp via TF32 MMA: out[q=64][a=64] = q[64][d64] . Wq[a][d64]^T ----
    {
        const int qr0 = 16 * (warp & 3), ac0 = 32 * (warp >> 2);
        float c[4][4];
#pragma unroll
        for (int nt = 0; nt < 4; nt++)
#pragma unroll
            for (int r = 0; r < 4; r++) c[nt][r] = 0.f;
#pragma unroll
        for (int kk = 0; kk < 8; kk++) {
            int d0 = kk * 8;
            unsigned A[4];
            A[0] = tf32c(s_q[(qr0 + grp) * 64 + d0 + thr]);
            A[1] = tf32c(s_q[(qr0 + grp + 8) * 64 + d0 + thr]);
            A[2] = tf32c(s_q[(qr0 + grp) * 64 + d0 + thr + 4]);
            A[3] = tf32c(s_q[(qr0 + grp + 8) * 64 + d0 + thr + 4]);
#pragma unroll
            for (int nt = 0; nt < 4; nt++) {
                unsigned Bf[2];
                Bf[0] = tf32c(s_W1[(ac0 + nt * 8 + grp) * 68 + d0 + thr]);
                Bf[1] = tf32c(s_W1[(ac0 + nt * 8 + grp) * 68 + d0 + thr + 4]);
                mma_tf32(c[nt], A, Bf);
            }
        }
        // epilogue writes s_qp (no alias with s_q/s_W1) — no barrier needed here
#pragma unroll
        for (int nt = 0; nt < 4; nt++) {
            int a0 = ac0 + nt * 8 + 2 * thr;
#pragma unroll
            for (int r = 0; r < 4; r++) {
                int aa = a0 + (r & 1);
                int qq = qr0 + grp + (r >= 2 ? 8 : 0);
                float v = c[nt][r] + s_bias[aa];
                if (aa < NF_) v = exp2f(v * LOG2E2);    // Eq = e^{2*qp}
                s_qp[aa * 68 + qq] = v;
            }
        }
    }
    __syncthreads();

    // ---- phase 2: stage x chunk [128][68] + Wk ----
#pragma unroll
    for (int i = 0; i < 8; i++) {
        int idx = tid + 256 * i; int k = idx >> 4, d4 = idx & 15;
        *(float4*)&s_xv[k * 68 + d4 * 4] =
            *(const float4*)&x[((size_t)b * KS_ + kc * KC_ + k) * KD_ + h * DH_ + d4 * 4];
    }
#pragma unroll
    for (int i = 0; i < 4; i++) {
        int idx = tid + 256 * i; int a = idx >> 4, d4 = idx & 15;
        *(float4*)&s_Wk[a * 68 + d4 * 4] = *(const float4*)&W[a * 128 + d4 * 4];
    }
    __syncthreads();

    // ---- kp via TF32 MMA: out[k=128][a=64] = x[k][d64] . Wk[a][d64]^T ----
    {
        const int kr0 = 16 * warp;
        float c[8][4];
#pragma unroll
        for (int nt = 0; nt < 8; nt++)
#pragma unroll
            for (int r = 0; r < 4; r++) c[nt][r] = 0.f;
#pragma unroll
        for (int kk = 0; kk < 8; kk++) {
            int d0 = kk * 8;
            unsigned A[4];
            A[0] = tf32c(s_xv[(kr0 + grp) * 68 + d0 + thr]);
            A[1] = tf32c(s_xv[(kr0 + grp + 8) * 68 + d0 + thr]);
            A[2] = tf32c(s_xv[(kr0 + grp) * 68 + d0 + thr + 4]);
            A[3] = tf32c(s_xv[(kr0 + grp + 8) * 68 + d0 + thr + 4]);
#pragma unroll
            for (int nt = 0; nt < 8; nt++) {
                unsigned Bf[2];
                Bf[0] = tf32c(s_Wk[(nt * 8 + grp) * 68 + d0 + thr]);
                Bf[1] = tf32c(s_Wk[(nt * 8 + grp) * 68 + d0 + thr + 4]);
                mma_tf32(c[nt], A, Bf);
            }
        }
        __syncthreads();   // s_q region (= s_kp dest) reads done CTA-wide before overwrite
#pragma unroll
        for (int nt = 0; nt < 8; nt++) {
            int a0 = nt * 8 + 2 * thr;
#pragma unroll
            for (int r = 0; r < 4; r++) {
                int aa = a0 + (r & 1);
                int kk2 = kr0 + grp + (r >= 2 ? 8 : 0);
                float v = c[nt][r];
                if (aa < NF_) v = -exp2f(v * LOG2E2);   // Ekn = -e^{2*kp}
                s_kp[aa * 132 + kk2] = v;
            }
        }
    }
    __syncthreads();

    // ---- phase 3: scores; FMA (a<NF, cubic Newton) and MUFU (a>=NF) interleaved ----
    const int q0 = ty * 4, k0 = tx * 8;
    const ull NEG1_2 = pk2(-1.f, -1.f);
    const ull ONE_2  = pk2(1.f, 1.f);

    float C = 0.f;
#pragma unroll
    for (int a = 0; a < NF_; a++) C += s_w2[a];

    ull acc2[4][4];
#pragma unroll
    for (int j = 0; j < 4; j++)
#pragma unroll
        for (int i = 0; i < 4; i++) acc2[j][i] = pk2(C, C);

#pragma unroll 2
    for (int a2 = 0; a2 < NF_; a2++) {
        {
            float4 eq  = *(float4*)&s_qp[a2 * 68 + q0];
            float4 ekA = *(float4*)&s_kp[a2 * 132 + k0];
            float4 ekB = *(float4*)&s_kp[a2 * 132 + k0 + 4];
            ull ek[4] = {pk2(ekA.x, ekA.y), pk2(ekA.z, ekA.w),
                         pk2(ekB.x, ekB.y), pk2(ekB.z, ekB.w)};
            float w2m = -2.f * s_w2[a2];
            ull w22 = pk2(w2m, w2m);
            float eqs[4] = {eq.x, eq.y, eq.z, eq.w};
#pragma unroll
            for (int j = 0; j < 4; j++) {
                ull eqj = pk2(eqs[j], eqs[j]);
#pragma unroll
                for (int i = 0; i < 4; i++) {
                    ull nv = ffma2(eqj, ek[i], NEG1_2);     // -(Eq*Ek + 1)
                    ull r  = rcp_seed2(nv);
                    ull e  = ffma2(nv, r, ONE_2);           // e = 1 - v*r
                    ull t  = ffma2(e, e, e);                // t = e + e^2
                    r = ffma2(r, t, r);                      // cubic Newton
                    acc2[j][i] = ffma2(w22, r, acc2[j][i]);
                }
            }
        }
        if (a2 < NM_) {
            int a = NF_ + a2;
            float4 qv = *(float4*)&s_qp[a * 68 + q0];
            float4 kA = *(float4*)&s_kp[a * 132 + k0];
            float4 kB = *(float4*)&s_kp[a * 132 + k0 + 4];
            float w2a = s_w2[a];
            ull w2p = pk2(w2a, w2a);
            ull kp2v[4] = {pk2(kA.x, kA.y), pk2(kA.z, kA.w),
                           pk2(kB.x, kB.y), pk2(kB.z, kB.w)};
            float qs[4] = {qv.x, qv.y, qv.z, qv.w};
#pragma unroll
            for (int j = 0; j < 4; j++) {
                ull qj2 = pk2(qs[j], qs[j]);
#pragma unroll
                for (int i = 0; i < 4; i++) {
                    float2 arg = upk2(fadd2(qj2, kp2v[i]));
                    float t0 = fast_tanh(arg.x);
                    float t1 = fast_tanh(arg.y);
                    acc2[j][i] = ffma2(w2p, pk2(t0, t1), acc2[j][i]);
                }
            }
        }
    }

    float acc[4][8];
#pragma unroll
    for (int j = 0; j < 4; j++)
#pragma unroll
        for (int i = 0; i < 4; i++) {
            float2 f = upk2(acc2[j][i]);
            acc[j][2 * i] = f.x; acc[j][2 * i + 1] = f.y;
        }

    // ---- phase 4: exp (no max; |score| <= sum|w2|), rowsum, p to smem ----
    float rowsum[4];
    {
        unsigned char mk[8];
        const unsigned char* mrow = &mask[b * KS_ + kc * KC_ + k0];
#pragma unroll
        for (int i = 0; i < 8; i++) mk[i] = mrow[i];
#pragma unroll
        for (int j = 0; j < 4; j++) {
            float s = 0.f;
#pragma unroll
            for (int i = 0; i < 8; i++) {
                float p = mk[i] ? 0.f : __expf(acc[j][i]);
                acc[j][i] = p;
                s += p;
            }
#pragma unroll
            for (int o = 8; o; o >>= 1) s += __shfl_xor_sync(0xffffffffu, s, o);
            rowsum[j] = s;
        }
    }
    __syncthreads();   // tanh reads of s_kp/s_qp done before p overwrites the region

#pragma unroll
    for (int j = 0; j < 4; j++) {
        *(float4*)&s_p[(q0 + j) * 132 + k0]     = make_float4(acc[j][0], acc[j][1], acc[j][2], acc[j][3]);
        *(float4*)&s_p[(q0 + j) * 132 + k0 + 4] = make_float4(acc[j][4], acc[j][5], acc[j][6], acc[j][7]);
    }
    if (tx == 0) {
#pragma unroll
        for (int j = 0; j < 4; j++)
            g_Sx[(bh * NC_ + kc) * QS_ + q0 + j] = rowsum[j];
    }
    __syncthreads();

    // ---- phase 5: pV via TF32 MMA: out[q=64][d=64] = p[q][k128] . V[k][d] ----
    {
        const int qr0 = 16 * (warp & 3), dc0 = 32 * (warp >> 2);
        float c[4][4];
#pragma unroll
        for (int nt = 0; nt < 4; nt++)
#pragma unroll
            for (int r = 0; r < 4; r++) c[nt][r] = 0.f;
#pragma unroll
        for (int kk = 0; kk < 16; kk++) {
            int kb = kk * 8;
            unsigned A[4];
            A[0] = tf32c(s_p[(qr0 + grp) * 132 + kb + thr]);
            A[1] = tf32c(s_p[(qr0 + grp + 8) * 132 + kb + thr]);
            A[2] = tf32c(s_p[(qr0 + grp) * 132 + kb + thr + 4]);
            A[3] = tf32c(s_p[(qr0 + grp + 8) * 132 + kb + thr + 4]);
#pragma unroll
            for (int nt = 0; nt < 4; nt++) {
                unsigned Bf[2];
                Bf[0] = tf32c(s_xv[(kb + thr) * 68 + dc0 + nt * 8 + grp]);
                Bf[1] = tf32c(s_xv[(kb + thr + 4) * 68 + dc0 + nt * 8 + grp]);
                mma_tf32(c[nt], A, Bf);
            }
        }
        const int pp = bh * NC_ + kc;
#pragma unroll
        for (int nt = 0; nt < 4; nt++) {
            int d0 = dc0 + nt * 8 + 2 * thr;
            int qa = qr0 + grp;
            *(float2*)&g_pout[(size_t)(pp * QS_ + qa) * DH_ + d0]     = make_float2(c[nt][0], c[nt][1]);
            *(float2*)&g_pout[(size_t)(pp * QS_ + qa + 8) * DH_ + d0] = make_float2(c[nt][2], c[nt][3]);
        }
    }

    // ---- last CTA per (b,h) merges the NC_ partials ----
    __threadfence();
    __syncthreads();
    if (tid == 0) {
        int old = atomicAdd(&g_cnt[bh], 1);
        *s_last = (old == NC_ - 1);
    }
    __syncthreads();
    if (*s_last) {
        __threadfence();
        const int qrow = tid >> 2, l4 = tid & 3;
        float St = 0.f;
#pragma unroll
        for (int p = 0; p < NC_; p++) St += g_Sx[(bh * NC_ + p) * QS_ + qrow];
        float inv = 1.f / St;
#pragma unroll
        for (int j = 0; j < 4; j++) {
            int dd = l4 * 16 + j * 4;
            float4 a = make_float4(0.f, 0.f, 0.f, 0.f);
#pragma unroll
            for (int p = 0; p < NC_; p++) {
                float4 v = *(const float4*)&g_pout[(size_t)((bh * NC_ + p) * QS_ + qrow) * DH_ + dd];
                a.x += v.x; a.y += v.y; a.z += v.z; a.w += v.w;
            }
            a.x *= inv; a.y *= inv; a.z *= inv; a.w *= inv;
            *(float4*)&out[(size_t)(b * QS_ + qrow) * QD_ + h * DH_ + dd] = a;
        }
        if (tid == 0) g_cnt[bh] = 0;   // reset for next graph replay
    }
}

// ---------------- launch ----------------
extern "C" void kernel_launch(void* const* d_in, const int* in_sizes, int n_in,
                              void* d_out, int out_size) {
    const float* x     = (const float*)d_in[0];
    const float* query = (const float*)d_in[1];
    const float* W     = (const float*)d_in[2];
    const float* bias  = (const float*)d_in[3];
    const float* w2    = (const float*)d_in[4];
    const unsigned char* mask = (const unsigned char*)d_in[5];
    float* out = (float*)d_out;

    cudaFuncSetAttribute(fused_kernel, cudaFuncAttributeMaxDynamicSharedMemorySize, SMF_BYTES);

    fused_kernel<<<dim3(NC_, H_, B_), 256, SMF_BYTES>>>(x, query, W, bias, w2, mask, out);
}

// round 17
// speedup vs baseline: 1.0796x; 1.0796x over previous
#include <cuda_runtime.h>

#define B_  8
#define H_  8
#define QS_ 64
#define KS_ 512
#define A_  64
#define DH_ 64
#define KC_ 128
#define NC_ 4
#define QD_ 512
#define KD_ 512
#define NF_ 35   // a in [0,NF): FMA-pipe cubic-Newton path; a in [NF,64): MUFU tanh
#define NM_ (A_ - NF_)

typedef unsigned long long ull;
typedef unsigned uint;

__device__ float g_pout[B_*H_*NC_*QS_*DH_];   // 4 MB
__device__ float g_Sx[B_*H_*NC_*QS_];

__device__ __forceinline__ float fast_tanh(float v) {
    float y; asm("tanh.approx.f32 %0, %1;" : "=f"(y) : "f"(v)); return y;
}
__device__ __forceinline__ ull pk2(float x, float y) {
    ull r; asm("mov.b64 %0, {%1, %2};" : "=l"(r) : "f"(x), "f"(y)); return r;
}
__device__ __forceinline__ float2 upk2(ull v) {
    float2 r; asm("mov.b64 {%0, %1}, %2;" : "=f"(r.x), "=f"(r.y) : "l"(v)); return r;
}
__device__ __forceinline__ ull ffma2(ull a, ull b, ull c) {
    ull d; asm("fma.rn.f32x2 %0, %1, %2, %3;" : "=l"(d) : "l"(a), "l"(b), "l"(c)); return d;
}
__device__ __forceinline__ ull fadd2(ull a, ull b) {
    ull d; asm("add.rn.f32x2 %0, %1, %2;" : "=l"(d) : "l"(a), "l"(b)); return d;
}
__device__ __forceinline__ ull rcp_seed2(ull nv) {
    unsigned lo, hi;
    asm("mov.b64 {%0, %1}, %2;" : "=r"(lo), "=r"(hi) : "l"(nv));
    lo = 0xFEF311C3u - lo;
    hi = 0xFEF311C3u - hi;
    ull r; asm("mov.b64 %0, {%1, %2};" : "=l"(r) : "r"(lo), "r"(hi));
    return r;
}
__device__ __forceinline__ uint tf32c(float f) {
    uint r; asm("cvt.rna.tf32.f32 %0, %1;" : "=r"(r) : "f"(f)); return r;
}
__device__ __forceinline__ uint4 tf32c4(float4 v) {
    uint4 u; u.x = tf32c(v.x); u.y = tf32c(v.y); u.z = tf32c(v.z); u.w = tf32c(v.w);
    return u;
}
__device__ __forceinline__ void mma_tf32(float* d, const uint* a, const uint* b) {
    asm volatile("mma.sync.aligned.m16n8k8.row.col.f32.tf32.tf32.f32 "
        "{%0,%1,%2,%3}, {%4,%5,%6,%7}, {%8,%9}, {%0,%1,%2,%3};"
        : "+f"(d[0]), "+f"(d[1]), "+f"(d[2]), "+f"(d[3])
        : "r"(a[0]), "r"(a[1]), "r"(a[2]), "r"(a[3]), "r"(b[0]), "r"(b[1]));
}

// ---------------- smem layout (bytes) — R15 layout; tf32 bit-pattern buffers ----------------
// s_xv @0 u32[128][68] (tf32 bits); s_q @34816 u32[64][64] (tf32, stride 64, ends 51200);
// s_W1 @51200 u32[64][68] (tf32); s_kp @34816 (alias, f32[64][132]);
// s_Wk @68608 (tf32); s_p @68608 (alias, u32[64][132] tf32); s_qp @86016 f32[64][68];
// s_bias @103424; s_w2 @103680
#define SMF_BYTES 103936

__global__ void __launch_bounds__(256, 2) fused_kernel(
    const float* __restrict__ x, const float* __restrict__ query,
    const float* __restrict__ W, const float* __restrict__ bias,
    const float* __restrict__ w2, const unsigned char* __restrict__ mask)
{
    extern __shared__ char sm[];
    uint*  s_xv  = (uint*)(sm);
    uint*  s_qu  = (uint*)(sm + 34816);
    uint*  s_W1  = (uint*)(sm + 51200);
    float* s_kp  = (float*)(sm + 34816);
    uint*  s_Wk  = (uint*)(sm + 68608);
    uint*  s_p   = (uint*)(sm + 68608);
    float* s_qp  = (float*)(sm + 86016);
    float* s_bias= (float*)(sm + 103424);
    float* s_w2  = (float*)(sm + 103680);

    const int kc = blockIdx.x, h = blockIdx.y, b = blockIdx.z;
    const int tid = threadIdx.x;
    const int tx = tid & 15, ty = tid >> 4;
    const int warp = tid >> 5, lane = tid & 31;
    const int grp = lane >> 2, thr = lane & 3;
    const int bh = b * H_ + h;
    const float LOG2E2 = 2.885390082f;   // 2*log2(e)

    if (tid < 64) { s_bias[tid] = bias[tid]; s_w2[tid] = w2[tid]; }

    // ---- phase 1: stage query (tf32 bits, stride 64) + Wq (tf32 bits) ----
#pragma unroll
    for (int i = 0; i < 4; i++) {
        int idx = tid + 256 * i; int q = idx >> 4, d4 = idx & 15;
        *(uint4*)&s_qu[q * 64 + d4 * 4] =
            tf32c4(*(const float4*)&query[(size_t)(b * QS_ + q) * QD_ + h * DH_ + d4 * 4]);
    }
#pragma unroll
    for (int i = 0; i < 4; i++) {
        int idx = tid + 256 * i; int a = idx >> 4, d4 = idx & 15;
        *(uint4*)&s_W1[a * 68 + d4 * 4] = tf32c4(*(const float4*)&W[a * 128 + 64 + d4 * 4]);
    }
    __syncthreads();

    // ---- qp via TF32 MMA: out[q=64][a=64] ----
    {
        const int qr0 = 16 * (warp & 3), ac0 = 32 * (warp >> 2);
        float c[4][4];
#pragma unroll
        for (int nt = 0; nt < 4; nt++)
#pragma unroll
            for (int r = 0; r < 4; r++) c[nt][r] = 0.f;
#pragma unroll
        for (int kk = 0; kk < 8; kk++) {
            int d0 = kk * 8;
            uint A[4];
            A[0] = s_qu[(qr0 + grp) * 64 + d0 + thr];
            A[1] = s_qu[(qr0 + grp + 8) * 64 + d0 + thr];
            A[2] = s_qu[(qr0 + grp) * 64 + d0 + thr + 4];
            A[3] = s_qu[(qr0 + grp + 8) * 64 + d0 + thr + 4];
#pragma unroll
            for (int nt = 0; nt < 4; nt++) {
                uint Bf[2];
                Bf[0] = s_W1[(ac0 + nt * 8 + grp) * 68 + d0 + thr];
                Bf[1] = s_W1[(ac0 + nt * 8 + grp) * 68 + d0 + thr + 4];
                mma_tf32(c[nt], A, Bf);
            }
        }
#pragma unroll
        for (int nt = 0; nt < 4; nt++) {
            int a0 = ac0 + nt * 8 + 2 * thr;
#pragma unroll
            for (int r = 0; r < 4; r++) {
                int aa = a0 + (r & 1);
                int qq = qr0 + grp + (r >= 2 ? 8 : 0);
                float v = c[nt][r] + s_bias[aa];
                if (aa < NF_) v = exp2f(v * LOG2E2);    // Eq = e^{2*qp}
                s_qp[aa * 68 + qq] = v;
            }
        }
    }
    __syncthreads();

    // ---- phase 2: stage x chunk (tf32 bits) + Wk (tf32 bits) ----
#pragma unroll
    for (int i = 0; i < 8; i++) {
        int idx = tid + 256 * i; int k = idx >> 4, d4 = idx & 15;
        *(uint4*)&s_xv[k * 68 + d4 * 4] =
            tf32c4(*(const float4*)&x[((size_t)b * KS_ + kc * KC_ + k) * KD_ + h * DH_ + d4 * 4]);
    }
#pragma unroll
    for (int i = 0; i < 4; i++) {
        int idx = tid + 256 * i; int a = idx >> 4, d4 = idx & 15;
        *(uint4*)&s_Wk[a * 68 + d4 * 4] = tf32c4(*(const float4*)&W[a * 128 + d4 * 4]);
    }
    __syncthreads();

    // ---- kp via TF32 MMA: out[k=128][a=64] ----
    {
        const int kr0 = 16 * warp;
        float c[8][4];
#pragma unroll
        for (int nt = 0; nt < 8; nt++)
#pragma unroll
            for (int r = 0; r < 4; r++) c[nt][r] = 0.f;
#pragma unroll
        for (int kk = 0; kk < 8; kk++) {
            int d0 = kk * 8;
            uint A[4];
            A[0] = s_xv[(kr0 + grp) * 68 + d0 + thr];
            A[1] = s_xv[(kr0 + grp + 8) * 68 + d0 + thr];
            A[2] = s_xv[(kr0 + grp) * 68 + d0 + thr + 4];
            A[3] = s_xv[(kr0 + grp + 8) * 68 + d0 + thr + 4];
#pragma unroll
            for (int nt = 0; nt < 8; nt++) {
                uint Bf[2];
                Bf[0] = s_Wk[(nt * 8 + grp) * 68 + d0 + thr];
                Bf[1] = s_Wk[(nt * 8 + grp) * 68 + d0 + thr + 4];
                mma_tf32(c[nt], A, Bf);
            }
        }
        __syncthreads();   // s_q region (= s_kp dest) reads done CTA-wide before overwrite
#pragma unroll
        for (int nt = 0; nt < 8; nt++) {
            int a0 = nt * 8 + 2 * thr;
#pragma unroll
            for (int r = 0; r < 4; r++) {
                int aa = a0 + (r & 1);
                int kk2 = kr0 + grp + (r >= 2 ? 8 : 0);
                float v = c[nt][r];
                if (aa < NF_) v = -exp2f(v * LOG2E2);   // Ekn = -e^{2*kp}
                s_kp[aa * 132 + kk2] = v;
            }
        }
    }
    __syncthreads();

    // ---- phase 3: scores; FMA (a<NF, cubic Newton) and MUFU (a>=NF) interleaved ----
    const int q0 = ty * 4, k0 = tx * 8;
    const ull NEG1_2 = pk2(-1.f, -1.f);
    const ull ONE_2  = pk2(1.f, 1.f);

    float C = 0.f;
#pragma unroll
    for (int a = 0; a < NF_; a++) C += s_w2[a];

    ull acc2[4][4];
#pragma unroll
    for (int j = 0; j < 4; j++)
#pragma unroll
        for (int i = 0; i < 4; i++) acc2[j][i] = pk2(C, C);

#pragma unroll 2
    for (int a2 = 0; a2 < NF_; a2++) {
        {
            float4 eq  = *(float4*)&s_qp[a2 * 68 + q0];
            float4 ekA = *(float4*)&s_kp[a2 * 132 + k0];
            float4 ekB = *(float4*)&s_kp[a2 * 132 + k0 + 4];
            ull ek[4] = {pk2(ekA.x, ekA.y), pk2(ekA.z, ekA.w),
                         pk2(ekB.x, ekB.y), pk2(ekB.z, ekB.w)};
            float w2m = -2.f * s_w2[a2];
            ull w22 = pk2(w2m, w2m);
            float eqs[4] = {eq.x, eq.y, eq.z, eq.w};
#pragma unroll
            for (int j = 0; j < 4; j++) {
                ull eqj = pk2(eqs[j], eqs[j]);
#pragma unroll
                for (int i = 0; i < 4; i++) {
                    ull nv = ffma2(eqj, ek[i], NEG1_2);     // -(Eq*Ek + 1)
                    ull r  = rcp_seed2(nv);
                    ull e  = ffma2(nv, r, ONE_2);           // e = 1 - v*r
                    ull t  = ffma2(e, e, e);                // t = e + e^2
                    r = ffma2(r, t, r);                      // cubic Newton
                    acc2[j][i] = ffma2(w22, r, acc2[j][i]);
                }
            }
        }
        if (a2 < NM_) {
            int a = NF_ + a2;
            float4 qv = *(float4*)&s_qp[a * 68 + q0];
            float4 kA = *(float4*)&s_kp[a * 132 + k0];
            float4 kB = *(float4*)&s_kp[a * 132 + k0 + 4];
            float w2a = s_w2[a];
            ull w2p = pk2(w2a, w2a);
            ull kp2v[4] = {pk2(kA.x, kA.y), pk2(kA.z, kA.w),
                           pk2(kB.x, kB.y), pk2(kB.z, kB.w)};
            float qs[4] = {qv.x, qv.y, qv.z, qv.w};
#pragma unroll
            for (int j = 0; j < 4; j++) {
                ull qj2 = pk2(qs[j], qs[j]);
#pragma unroll
                for (int i = 0; i < 4; i++) {
                    float2 arg = upk2(fadd2(qj2, kp2v[i]));
                    float t0 = fast_tanh(arg.x);
                    float t1 = fast_tanh(arg.y);
                    acc2[j][i] = ffma2(w2p, pk2(t0, t1), acc2[j][i]);
                }
            }
        }
    }

    float acc[4][8];
#pragma unroll
    for (int j = 0; j < 4; j++)
#pragma unroll
        for (int i = 0; i < 4; i++) {
            float2 f = upk2(acc2[j][i]);
            acc[j][2 * i] = f.x; acc[j][2 * i + 1] = f.y;
        }

    // ---- phase 4: exp (no max), rowsum, p to smem as tf32 bits ----
    float rowsum[4];
    {
        unsigned char mk[8];
        const unsigned char* mrow = &mask[b * KS_ + kc * KC_ + k0];
#pragma unroll
        for (int i = 0; i < 8; i++) mk[i] = mrow[i];
#pragma unroll
        for (int j = 0; j < 4; j++) {
            float s = 0.f;
#pragma unroll
            for (int i = 0; i < 8; i++) {
                float p = mk[i] ? 0.f : __expf(acc[j][i]);
                acc[j][i] = p;
                s += p;
            }
#pragma unroll
            for (int o = 8; o; o >>= 1) s += __shfl_xor_sync(0xffffffffu, s, o);
            rowsum[j] = s;
        }
    }
    __syncthreads();   // tanh reads of s_kp/s_qp done before p overwrites the region

#pragma unroll
    for (int j = 0; j < 4; j++) {
        uint4 u0, u1;
        u0.x = tf32c(acc[j][0]); u0.y = tf32c(acc[j][1]);
        u0.z = tf32c(acc[j][2]); u0.w = tf32c(acc[j][3]);
        u1.x = tf32c(acc[j][4]); u1.y = tf32c(acc[j][5]);
        u1.z = tf32c(acc[j][6]); u1.w = tf32c(acc[j][7]);
        *(uint4*)&s_p[(q0 + j) * 132 + k0]     = u0;
        *(uint4*)&s_p[(q0 + j) * 132 + k0 + 4] = u1;
    }
    if (tx == 0) {
#pragma unroll
        for (int j = 0; j < 4; j++)
            g_Sx[(bh * NC_ + kc) * QS_ + q0 + j] = rowsum[j];
    }
    __syncthreads();

    // ---- phase 5: pV via TF32 MMA: out[q=64][d=64] = p[q][k128] . V[k][d] ----
    {
        const int qr0 = 16 * (warp & 3), dc0 = 32 * (warp >> 2);
        float c[4][4];
#pragma unroll
        for (int nt = 0; nt < 4; nt++)
#pragma unroll
            for (int r = 0; r < 4; r++) c[nt][r] = 0.f;
#pragma unroll
        for (int kk = 0; kk < 16; kk++) {
            int kb = kk * 8;
            uint A[4];
            A[0] = s_p[(qr0 + grp) * 132 + kb + thr];
            A[1] = s_p[(qr0 + grp + 8) * 132 + kb + thr];
            A[2] = s_p[(qr0 + grp) * 132 + kb + thr + 4];
            A[3] = s_p[(qr0 + grp + 8) * 132 + kb + thr + 4];
#pragma unroll
            for (int nt = 0; nt < 4; nt++) {
                uint Bf[2];
                Bf[0] = s_xv[(kb + thr) * 68 + dc0 + nt * 8 + grp];
                Bf[1] = s_xv[(kb + thr + 4) * 68 + dc0 + nt * 8 + grp];
                mma_tf32(c[nt], A, Bf);
            }
        }
        const int pp = bh * NC_ + kc;
#pragma unroll
        for (int nt = 0; nt < 4; nt++) {
            int d0 = dc0 + nt * 8 + 2 * thr;
            int qa = qr0 + grp;
            *(float2*)&g_pout[(size_t)(pp * QS_ + qa) * DH_ + d0]     = make_float2(c[nt][0], c[nt][1]);
            *(float2*)&g_pout[(size_t)(pp * QS_ + qa + 8) * DH_ + d0] = make_float2(c[nt][2], c[nt][3]);
        }
    }
}

// ---------------- combine: merge 4 chunk partials, 1 float2 per thread ----------------
__global__ void __launch_bounds__(256) combine_kernel(float* __restrict__ out)
{
    const int idx = blockIdx.x * 256 + threadIdx.x;   // 0..2047 per bh
    const int bh = blockIdx.y;
    const int b = bh >> 3, h = bh & 7;
    const int q = idx >> 5, d0 = (idx & 31) * 2;

    float S = 0.f;
#pragma unroll
    for (int c = 0; c < NC_; c++) S += g_Sx[(bh * NC_ + c) * QS_ + q];
    float inv = 1.f / S;

    float2 a = make_float2(0.f, 0.f);
#pragma unroll
    for (int c = 0; c < NC_; c++) {
        float2 v = *(const float2*)&g_pout[(size_t)((bh * NC_ + c) * QS_ + q) * DH_ + d0];
        a.x += v.x; a.y += v.y;
    }
    a.x *= inv; a.y *= inv;

    *(float2*)&out[(size_t)(b * QS_ + q) * QD_ + h * DH_ + d0] = a;
}

// ---------------- launch ----------------
extern "C" void kernel_launch(void* const* d_in, const int* in_sizes, int n_in,
                              void* d_out, int out_size) {
    const float* x     = (const float*)d_in[0];
    const float* query = (const float*)d_in[1];
    const float* W     = (const float*)d_in[2];
    const float* bias  = (const float*)d_in[3];
    const float* w2    = (const float*)d_in[4];
    const unsigned char* mask = (const unsigned char*)d_in[5];
    float* out = (float*)d_out;

    cudaFuncSetAttribute(fused_kernel, cudaFuncAttributeMaxDynamicSharedMemorySize, SMF_BYTES);

    fused_kernel<<<dim3(NC_, H_, B_), 256, SMF_BYTES>>>(x, query, W, bias, w2, mask);
    combine_kernel<<<dim3(8, B_ * H_), 256>>>(out);
}